// round 12
// baseline (speedup 1.0000x reference)
#include <cuda_runtime.h>
#include <cuda_fp16.h>
#include <stdint.h>
#include <math.h>

// Problem constants
#define BATCH 2
#define NTOK  4096
#define CDIM  256
#define ADIM  128
#define NH    4
#define HDIM  32
#define QSCALE 0.17677669529663688f  // 1/sqrt(32)

// Scratch (allocation-free: __device__ globals) — fp16 dataflow
__device__ __half g_Q[BATCH * NH * NTOK * HDIM];   // prescaled by QSCALE
__device__ __half g_K[BATCH * NH * NTOK * HDIM];
__device__ __half g_V[BATCH * NH * NTOK * HDIM];
__device__ __half g_AO[BATCH * NTOK * ADIM];

// m16n8k16 fp16 HMMA, fp32 accum, D=C in place (baseline PTX, compute_103-safe)
#define MMA_F16(d, a, b0, b1) \
    asm volatile("mma.sync.aligned.m16n8k16.row.col.f32.f16.f16.f32 " \
        "{%0,%1,%2,%3}, {%4,%5,%6,%7}, {%8,%9}, {%0,%1,%2,%3};" \
        : "+f"((d)[0]), "+f"((d)[1]), "+f"((d)[2]), "+f"((d)[3]) \
        : "r"((a)[0]), "r"((a)[1]), "r"((a)[2]), "r"((a)[3]), "r"(b0), "r"(b1))

__device__ __forceinline__ uint32_t packh2(float a, float b) {
    __half2 t = __floats2half2_rn(a, b);   // low = a
    return *reinterpret_cast<uint32_t*>(&t);
}

// ---------------------------------------------------------------------------
// Kernel 1: fused QKV projection via HMMA.
// grid = (8192/128 = 64, 3), 256 threads = 8 warps (4 M x 2 N).
// CTA tile M=128 (2 m-frags per warp), N=128(all), K=256 loop, prefetch d=1.
// W^T staged in dyn smem (stride 264 halves, conflict-free B-frag LDS).
// Output fp16 [b,head,tok,dim], Q prescaled.
// ---------------------------------------------------------------------------
#define WT_STRIDE 264
__global__ void __launch_bounds__(256) qkv_proj_mma(const float* __restrict__ query,
                                                    const float* __restrict__ context,
                                                    const float* __restrict__ Wq,
                                                    const float* __restrict__ Wk,
                                                    const float* __restrict__ Wv) {
    extern __shared__ __half WT[];   // [128][WT_STRIDE]
    const int bm = blockIdx.x;
    const int which = blockIdx.y;
    const float* X = (which == 0) ? query : context;
    const float* W = (which == 0) ? Wq : ((which == 1) ? Wk : Wv);
    __half* Og = (which == 0) ? g_Q : ((which == 1) ? g_K : g_V);

    const int t = threadIdx.x;
    const int w = t >> 5, lane = t & 31;
    const int g = lane >> 2, q = lane & 3;
    const int wm = w >> 1, wn = w & 1;

    // ---- stage W^T (fp16): thread t covers n = t&127, k-half (t>>7) ----
    {
        const int n = t & 127, kb = (t >> 7) * 128;
        #pragma unroll
        for (int kk = 0; kk < 128; kk += 8) {
            const int k0 = kb + kk;
            __half h[8];
            #pragma unroll
            for (int j = 0; j < 8; j++)
                h[j] = __float2half_rn(W[(size_t)(k0 + j) * ADIM + n]);
            *(uint4*)&WT[n * WT_STRIDE + k0] = *(uint4*)h;
        }
    }
    __syncthreads();

    const int r0 = bm * 128 + wm * 16 + g;     // global token row; second frag at +64
    float acc[2][8][4] = {};
    const __half* Wrow = &WT[(wn * 64 + g) * WT_STRIDE + 2 * q];

    uint32_t af[2][4];
    #pragma unroll
    for (int mf = 0; mf < 2; mf++) {
        const size_t r = (size_t)(r0 + mf * 64) * CDIM;
        const float2 x0 = *(const float2*)&X[r + 2 * q];
        const float2 x1 = *(const float2*)&X[r + 8 * CDIM + 2 * q];
        const float2 x2 = *(const float2*)&X[r + 8 + 2 * q];
        const float2 x3 = *(const float2*)&X[r + 8 * CDIM + 8 + 2 * q];
        af[mf][0] = packh2(x0.x, x0.y); af[mf][1] = packh2(x1.x, x1.y);
        af[mf][2] = packh2(x2.x, x2.y); af[mf][3] = packh2(x3.x, x3.y);
    }

    #pragma unroll
    for (int k0 = 0; k0 < CDIM; k0 += 16) {
        uint32_t afn[2][4];
        if (k0 + 16 < CDIM) {
            const int kn = k0 + 16;
            #pragma unroll
            for (int mf = 0; mf < 2; mf++) {
                const size_t r = (size_t)(r0 + mf * 64) * CDIM + kn;
                const float2 x0 = *(const float2*)&X[r + 2 * q];
                const float2 x1 = *(const float2*)&X[r + 8 * CDIM + 2 * q];
                const float2 x2 = *(const float2*)&X[r + 8 + 2 * q];
                const float2 x3 = *(const float2*)&X[r + 8 * CDIM + 8 + 2 * q];
                afn[mf][0] = packh2(x0.x, x0.y); afn[mf][1] = packh2(x1.x, x1.y);
                afn[mf][2] = packh2(x2.x, x2.y); afn[mf][3] = packh2(x3.x, x3.y);
            }
        }
        #pragma unroll
        for (int nf = 0; nf < 8; nf++) {
            const uint32_t b0 = *(const uint32_t*)&Wrow[nf * 8 * WT_STRIDE + k0];
            const uint32_t b1 = *(const uint32_t*)&Wrow[nf * 8 * WT_STRIDE + k0 + 8];
            MMA_F16(acc[0][nf], af[0], b0, b1);
            MMA_F16(acc[1][nf], af[1], b0, b1);
        }
        if (k0 + 16 < CDIM) {
            #pragma unroll
            for (int mf = 0; mf < 2; mf++)
                #pragma unroll
                for (int j = 0; j < 4; j++) af[mf][j] = afn[mf][j];
        }
    }

    // ---- epilogue: fp16 out, [b,head,tok,32], Q prescaled ----
    const float scale = (which == 0) ? QSCALE : 1.0f;
    #pragma unroll
    for (int mf = 0; mf < 2; mf++) {
        const int gr = r0 + mf * 64;
        const int bb = gr >> 12, ii = gr & 4095;
        #pragma unroll
        for (int nf = 0; nf < 8; nf++) {
            const int c = wn * 64 + nf * 8 + 2 * q;
            const int hh = c >> 5, dd = c & 31;
            const size_t base = (((size_t)(bb * NH + hh) * NTOK) + ii) * HDIM + dd;
            *(uint32_t*)&Og[base] = packh2(acc[mf][nf][0] * scale, acc[mf][nf][1] * scale);
            *(uint32_t*)&Og[base + 8 * HDIM] = packh2(acc[mf][nf][2] * scale, acc[mf][nf][3] * scale);
        }
    }
}

// ---------------------------------------------------------------------------
// Kernel 2: flash attention, fp16 in/out, fp32 exp + FADD row sums.
// grid = (32, 8), 256 threads = 8 warps x 16 query rows; BN = 128 keys/round
// (two 64-key sub-tiles per sync round).
// ---------------------------------------------------------------------------
__global__ void __launch_bounds__(256) flash_attn_mma() {
    __shared__ __half Ks[128][40];      // [key][dim], stride 40 halves
    __shared__ __half VTs[2][32][72];   // per 64-key half: [dim][token-pair words]

    const int qt = blockIdx.x;
    const int bh = blockIdx.y;
    const int t  = threadIdx.x;
    const int w  = t >> 5;
    const int lane = t & 31;
    const int g = lane >> 2;
    const int q = lane & 3;

    const __half* Qg = g_Q + ((size_t)bh * NTOK + (size_t)qt * 128) * HDIM;
    const __half* Kg = g_K + (size_t)bh * NTOK * HDIM;
    const __half* Vg = g_V + (size_t)bh * NTOK * HDIM;

    // ---- Q A-fragments straight from global (prescaled fp16) ----
    const int r0l = w * 16 + g;
    uint32_t qf[2][4];
    #pragma unroll
    for (int kf = 0; kf < 2; kf++) {
        qf[kf][0] = *(const uint32_t*)&Qg[(size_t)r0l * HDIM + kf * 16 + 2 * q];
        qf[kf][1] = *(const uint32_t*)&Qg[(size_t)(r0l + 8) * HDIM + kf * 16 + 2 * q];
        qf[kf][2] = *(const uint32_t*)&Qg[(size_t)r0l * HDIM + kf * 16 + 2 * q + 8];
        qf[kf][3] = *(const uint32_t*)&Qg[(size_t)(r0l + 8) * HDIM + kf * 16 + 2 * q + 8];
    }

    float oacc[4][4] = {};
    float lsum0 = 0.0f, lsum1 = 0.0f;

    const int kr = t >> 2;      // staging: key/token row 0..63 (per half)
    const int q4 = t & 3;       // staging: dim chunk

    for (int kt = 0; kt < NTOK / 128; kt++) {
        // prefetch both 64-key halves (fp16, 16B per thread per tensor per half)
        const size_t rowa = ((size_t)kt * 128 + kr) * HDIM + q4 * 8;
        const size_t rowb = rowa + (size_t)64 * HDIM;
        const uint4 kva = *(const uint4*)&Kg[rowa];
        const uint4 kvb = *(const uint4*)&Kg[rowb];
        const uint4 vva = *(const uint4*)&Vg[rowa];
        const uint4 vvb = *(const uint4*)&Vg[rowb];
        __syncthreads();   // previous round's compute done reading smem

        // K tiles [key][dim]: rotated u32 stores (conflict-free)
        {
            uint32_t ka[4] = {kva.x, kva.y, kva.z, kva.w};
            uint32_t kb[4] = {kvb.x, kvb.y, kvb.z, kvb.w};
            #pragma unroll
            for (int j = 0; j < 4; j++) {
                const int jj = (j + kr) & 3;
                *(uint32_t*)&Ks[kr][q4 * 8 + 2 * jj] = ka[jj];
                *(uint32_t*)&Ks[64 + kr][q4 * 8 + 2 * jj] = kb[jj];
            }
        }
        // V^T tiles [dim][token]: shfl partner token, byte_perm merge, swizzled
        {
            const int pk = kr & 1;
            uint32_t va[4] = {vva.x, vva.y, vva.z, vva.w};
            uint32_t vb[4] = {vvb.x, vvb.y, vvb.z, vvb.w};
            #pragma unroll
            for (int j = 0; j < 4; j++) {
                const uint32_t pa = __shfl_xor_sync(0xffffffffu, va[j], 4);
                const uint32_t pb = __shfl_xor_sync(0xffffffffu, vb[j], 4);
                const uint32_t worda = pk ? __byte_perm(pa, va[j], 0x7632)
                                          : __byte_perm(va[j], pa, 0x5410);
                const uint32_t wordb = pk ? __byte_perm(pb, vb[j], 0x7632)
                                          : __byte_perm(vb[j], pb, 0x5410);
                const int d = q4 * 8 + 2 * j + pk;
                const int pos = (kr >> 1) ^ (((d >> 3) & 3) << 3);
                *(uint32_t*)&VTs[0][d][2 * pos] = worda;
                *(uint32_t*)&VTs[1][d][2 * pos] = wordb;
            }
        }
        __syncthreads();

        #pragma unroll
        for (int sub = 0; sub < 2; sub++) {
            // ---- S = Q K^T ----
            float sacc[8][4];
            #pragma unroll
            for (int nf = 0; nf < 8; nf++) {
                sacc[nf][0] = sacc[nf][1] = sacc[nf][2] = sacc[nf][3] = 0.0f;
                const int key = sub * 64 + nf * 8 + g;
                #pragma unroll
                for (int kf = 0; kf < 2; kf++) {
                    const uint32_t b0 = *(const uint32_t*)&Ks[key][kf * 16 + 2 * q];
                    const uint32_t b1 = *(const uint32_t*)&Ks[key][kf * 16 + 2 * q + 8];
                    MMA_F16(sacc[nf], qf[kf], b0, b1);
                }
            }

            // ---- exp (fp32 MUFU), fp32 row sums, pack P frags (fp16) ----
            uint32_t pf[4][4];
            #pragma unroll
            for (int nf = 0; nf < 8; nf++) {
                const float p0 = __expf(sacc[nf][0]);
                const float p1 = __expf(sacc[nf][1]);
                const float p2 = __expf(sacc[nf][2]);
                const float p3 = __expf(sacc[nf][3]);
                lsum0 += p0 + p1;
                lsum1 += p2 + p3;
                const int kp = nf >> 1, half = nf & 1;
                pf[kp][half * 2 + 0] = packh2(p0, p1);
                pf[kp][half * 2 + 1] = packh2(p2, p3);
            }

            // ---- O += P V ----
            #pragma unroll
            for (int of = 0; of < 4; of++) {
                const int d = of * 8 + g;
                const int sw = ((d >> 3) & 3) << 3;
                #pragma unroll
                for (int kp = 0; kp < 4; kp++) {
                    const int lw0 = q + 8 * kp;
                    const uint32_t b0 = *(const uint32_t*)&VTs[sub][d][2 * (lw0 ^ sw)];
                    const uint32_t b1 = *(const uint32_t*)&VTs[sub][d][2 * ((lw0 + 4) ^ sw)];
                    MMA_F16(oacc[of], pf[kp], b0, b1);
                }
            }
        }
    }

    // ---- reduce row sums across the 4 lanes of each row group ----
    lsum0 += __shfl_xor_sync(0xffffffffu, lsum0, 1);
    lsum0 += __shfl_xor_sync(0xffffffffu, lsum0, 2);
    lsum1 += __shfl_xor_sync(0xffffffffu, lsum1, 1);
    lsum1 += __shfl_xor_sync(0xffffffffu, lsum1, 2);
    const float inv0 = 1.0f / lsum0;
    const float inv1 = 1.0f / lsum1;

    // ---- write O (fp16) ----
    {
        const int b = bh >> 2, h = bh & 3;
        const int grow0 = qt * 128 + r0l;
        __half* dst0 = g_AO + ((size_t)(b * NTOK + grow0)) * ADIM + h * HDIM;
        __half* dst1 = dst0 + 8 * ADIM;
        #pragma unroll
        for (int of = 0; of < 4; of++) {
            const int c = of * 8 + 2 * q;
            *(uint32_t*)&dst0[c] = packh2(oacc[of][0] * inv0, oacc[of][1] * inv0);
            *(uint32_t*)&dst1[c] = packh2(oacc[of][2] * inv1, oacc[of][3] * inv1);
        }
    }
}

// ---------------------------------------------------------------------------
// Kernel 3: output projection via HMMA.  g_AO(fp16)[8192,128] @ Wo[128,256].
// grid = (2, 128), 256 threads = 8 warps (4 M x 2 N). CTA tile M=64, N=128.
// ---------------------------------------------------------------------------
#define WOT_STRIDE 136
__global__ void __launch_bounds__(256) oproj_mma(const float* __restrict__ Wo,
                                                 float* __restrict__ out) {
    __shared__ __half WoT[128 * WOT_STRIDE];
    const int bn = blockIdx.x;
    const int bm = blockIdx.y;
    const int t = threadIdx.x;
    const int w = t >> 5, lane = t & 31;
    const int g = lane >> 2, q = lane & 3;
    const int wm = w >> 1, wn = w & 1;

    {
        const int n = t & 127, kb = (t >> 7) * 64;
        #pragma unroll
        for (int kk = 0; kk < 64; kk += 8) {
            const int k0 = kb + kk;
            __half h[8];
            #pragma unroll
            for (int j = 0; j < 8; j++)
                h[j] = __float2half_rn(Wo[(size_t)(k0 + j) * CDIM + bn * 128 + n]);
            *(uint4*)&WoT[n * WOT_STRIDE + k0] = *(uint4*)h;
        }
    }
    __syncthreads();

    const int r0 = bm * 64 + wm * 16 + g;
    float acc[8][4] = {};
    const __half* Arow0 = g_AO + (size_t)r0 * ADIM;
    const __half* Wrow = &WoT[(wn * 64 + g) * WOT_STRIDE + 2 * q];

    #pragma unroll
    for (int k0 = 0; k0 < ADIM; k0 += 16) {
        uint32_t af[4];
        af[0] = *(const uint32_t*)&Arow0[k0 + 2 * q];
        af[1] = *(const uint32_t*)&Arow0[8 * ADIM + k0 + 2 * q];
        af[2] = *(const uint32_t*)&Arow0[k0 + 2 * q + 8];
        af[3] = *(const uint32_t*)&Arow0[8 * ADIM + k0 + 2 * q + 8];
        #pragma unroll
        for (int nf = 0; nf < 8; nf++) {
            const uint32_t b0 = *(const uint32_t*)&Wrow[nf * 8 * WOT_STRIDE + k0];
            const uint32_t b1 = *(const uint32_t*)&Wrow[nf * 8 * WOT_STRIDE + k0 + 8];
            MMA_F16(acc[nf], af, b0, b1);
        }
    }

    #pragma unroll
    for (int nf = 0; nf < 8; nf++) {
        const int c = bn * 128 + wn * 64 + nf * 8 + 2 * q;
        *(float2*)&out[(size_t)r0 * CDIM + c] = make_float2(acc[nf][0], acc[nf][1]);
        *(float2*)&out[(size_t)(r0 + 8) * CDIM + c] = make_float2(acc[nf][2], acc[nf][3]);
    }
}

// ---------------------------------------------------------------------------
extern "C" void kernel_launch(void* const* d_in, const int* in_sizes, int n_in,
                              void* d_out, int out_size) {
    const float* query   = (const float*)d_in[0];
    const float* context = (const float*)d_in[1];
    const float* Wq      = (const float*)d_in[2];
    const float* Wk      = (const float*)d_in[3];
    const float* Wv      = (const float*)d_in[4];
    const float* Wo      = (const float*)d_in[5];
    float* out = (float*)d_out;

    const int qkv_smem = 128 * WT_STRIDE * 2;  // 67.6 KB > 48 KB -> opt-in
    cudaFuncSetAttribute(qkv_proj_mma, cudaFuncAttributeMaxDynamicSharedMemorySize, qkv_smem);

    qkv_proj_mma<<<dim3(64, 3), 256, qkv_smem>>>(query, context, Wq, Wk, Wv);
    flash_attn_mma<<<dim3(NTOK / 128, NH * BATCH), 256>>>();
    oproj_mma<<<dim3(2, 128), 256>>>(Wo, out);
}

// round 13
// speedup vs baseline: 1.1474x; 1.1474x over previous
#include <cuda_runtime.h>
#include <cuda_fp16.h>
#include <stdint.h>
#include <math.h>

// Problem constants
#define BATCH 2
#define NTOK  4096
#define CDIM  256
#define ADIM  128
#define NH    4
#define HDIM  32
#define QSCALE 0.17677669529663688f   // 1/sqrt(32)
#define LOG2E  1.4426950408889634f
#define QSCALE_L2E (QSCALE * LOG2E)   // folded: S comes out in log2 domain

// Scratch (allocation-free: __device__ globals) — fp16 dataflow
__device__ __half g_Q[BATCH * NH * NTOK * HDIM];   // prescaled by QSCALE*LOG2E
__device__ __half g_K[BATCH * NH * NTOK * HDIM];
__device__ __half g_V[BATCH * NH * NTOK * HDIM];
__device__ __half g_AO[BATCH * NTOK * ADIM];

// m16n8k16 fp16 HMMA, fp32 accum, D=C in place (baseline PTX, compute_103-safe)
#define MMA_F16(d, a, b0, b1) \
    asm volatile("mma.sync.aligned.m16n8k16.row.col.f32.f16.f16.f32 " \
        "{%0,%1,%2,%3}, {%4,%5,%6,%7}, {%8,%9}, {%0,%1,%2,%3};" \
        : "+f"((d)[0]), "+f"((d)[1]), "+f"((d)[2]), "+f"((d)[3]) \
        : "r"((a)[0]), "r"((a)[1]), "r"((a)[2]), "r"((a)[3]), "r"(b0), "r"(b1))

__device__ __forceinline__ uint32_t packh2(float a, float b) {
    __half2 t = __floats2half2_rn(a, b);   // low = a
    return *reinterpret_cast<uint32_t*>(&t);
}
__device__ __forceinline__ uint32_t ex2h2(uint32_t x) {
    uint32_t r;
    asm("ex2.approx.f16x2 %0, %1;" : "=r"(r) : "r"(x));
    return r;
}
__device__ __forceinline__ uint32_t hadd2u(uint32_t a, uint32_t b) {
    uint32_t r;
    asm("add.f16x2 %0, %1, %2;" : "=r"(r) : "r"(a), "r"(b));
    return r;
}

// ---------------------------------------------------------------------------
// Kernel 1: fused QKV projection via HMMA (R10 config).
// grid = (128, 3), 256 threads = 8 warps (4 M x 2 N). CTA tile M=64, N=128.
// ---------------------------------------------------------------------------
#define WT_STRIDE 264
__global__ void __launch_bounds__(256) qkv_proj_mma(const float* __restrict__ query,
                                                    const float* __restrict__ context,
                                                    const float* __restrict__ Wq,
                                                    const float* __restrict__ Wk,
                                                    const float* __restrict__ Wv) {
    extern __shared__ __half WT[];   // [128][WT_STRIDE]
    const int bm = blockIdx.x;
    const int which = blockIdx.y;
    const float* X = (which == 0) ? query : context;
    const float* W = (which == 0) ? Wq : ((which == 1) ? Wk : Wv);
    __half* Og = (which == 0) ? g_Q : ((which == 1) ? g_K : g_V);

    const int t = threadIdx.x;
    const int w = t >> 5, lane = t & 31;
    const int g = lane >> 2, q = lane & 3;
    const int wm = w >> 1, wn = w & 1;

    // ---- stage W^T (fp16) ----
    {
        const int n = t & 127, kb = (t >> 7) * 128;
        #pragma unroll
        for (int kk = 0; kk < 128; kk += 8) {
            const int k0 = kb + kk;
            __half h[8];
            #pragma unroll
            for (int j = 0; j < 8; j++)
                h[j] = __float2half_rn(W[(size_t)(k0 + j) * ADIM + n]);
            *(uint4*)&WT[n * WT_STRIDE + k0] = *(uint4*)h;
        }
    }
    __syncthreads();

    const int r0 = bm * 64 + wm * 16 + g;
    float acc[8][4] = {};
    const __half* Wrow = &WT[(wn * 64 + g) * WT_STRIDE + 2 * q];

    #pragma unroll
    for (int k0 = 0; k0 < CDIM; k0 += 16) {
        uint32_t af[4];
        {
            const float2 x0 = *(const float2*)&X[(size_t)r0 * CDIM + k0 + 2 * q];
            const float2 x1 = *(const float2*)&X[(size_t)(r0 + 8) * CDIM + k0 + 2 * q];
            const float2 x2 = *(const float2*)&X[(size_t)r0 * CDIM + k0 + 8 + 2 * q];
            const float2 x3 = *(const float2*)&X[(size_t)(r0 + 8) * CDIM + k0 + 8 + 2 * q];
            af[0] = packh2(x0.x, x0.y);
            af[1] = packh2(x1.x, x1.y);
            af[2] = packh2(x2.x, x2.y);
            af[3] = packh2(x3.x, x3.y);
        }
        #pragma unroll
        for (int nf = 0; nf < 8; nf++) {
            const uint32_t b0 = *(const uint32_t*)&Wrow[nf * 8 * WT_STRIDE + k0];
            const uint32_t b1 = *(const uint32_t*)&Wrow[nf * 8 * WT_STRIDE + k0 + 8];
            MMA_F16(acc[nf], af, b0, b1);
        }
    }

    // ---- epilogue: fp16 out, [b,head,tok,32], Q prescaled by QSCALE*LOG2E ----
    const float scale = (which == 0) ? QSCALE_L2E : 1.0f;
    const int bb = r0 >> 12, ii = r0 & 4095;
    #pragma unroll
    for (int nf = 0; nf < 8; nf++) {
        const int c = wn * 64 + nf * 8 + 2 * q;
        const int hh = c >> 5, dd = c & 31;
        const size_t base = (((size_t)(bb * NH + hh) * NTOK) + ii) * HDIM + dd;
        *(uint32_t*)&Og[base] = packh2(acc[nf][0] * scale, acc[nf][1] * scale);
        *(uint32_t*)&Og[base + 8 * HDIM] = packh2(acc[nf][2] * scale, acc[nf][3] * scale);
    }
}

// ---------------------------------------------------------------------------
// Kernel 2: flash attention. fp16 in/out, ex2.f16x2 exp (S already log2-scaled),
// rowsum via HADD2 on packed P words (fma pipe, hidden under tensor issue).
// grid = (32, 8), 256 threads = 8 warps x 16 query rows; 128 keys per sync round.
// ---------------------------------------------------------------------------
__global__ void __launch_bounds__(256) flash_attn_mma() {
    __shared__ __half Ks[128][40];      // [key][dim], stride 40 halves
    __shared__ __half VTs[2][32][72];   // per 64-key half: [dim][token-pair words]

    const int qt = blockIdx.x;
    const int bh = blockIdx.y;
    const int t  = threadIdx.x;
    const int w  = t >> 5;
    const int lane = t & 31;
    const int g = lane >> 2;
    const int q = lane & 3;

    const __half* Qg = g_Q + ((size_t)bh * NTOK + (size_t)qt * 128) * HDIM;
    const __half* Kg = g_K + (size_t)bh * NTOK * HDIM;
    const __half* Vg = g_V + (size_t)bh * NTOK * HDIM;

    // ---- Q A-fragments straight from global (prescaled fp16) ----
    const int r0l = w * 16 + g;
    uint32_t qf[2][4];
    #pragma unroll
    for (int kf = 0; kf < 2; kf++) {
        qf[kf][0] = *(const uint32_t*)&Qg[(size_t)r0l * HDIM + kf * 16 + 2 * q];
        qf[kf][1] = *(const uint32_t*)&Qg[(size_t)(r0l + 8) * HDIM + kf * 16 + 2 * q];
        qf[kf][2] = *(const uint32_t*)&Qg[(size_t)r0l * HDIM + kf * 16 + 2 * q + 8];
        qf[kf][3] = *(const uint32_t*)&Qg[(size_t)(r0l + 8) * HDIM + kf * 16 + 2 * q + 8];
    }

    float oacc[4][4] = {};
    float lsum0 = 0.0f, lsum1 = 0.0f;

    const int kr = t >> 2;      // staging: key/token row 0..63 (per half)
    const int q4 = t & 3;       // staging: dim chunk

    for (int kt = 0; kt < NTOK / 128; kt++) {
        // prefetch both 64-key halves (16B per thread per tensor per half)
        const size_t rowa = ((size_t)kt * 128 + kr) * HDIM + q4 * 8;
        const size_t rowb = rowa + (size_t)64 * HDIM;
        const uint4 kva = *(const uint4*)&Kg[rowa];
        const uint4 kvb = *(const uint4*)&Kg[rowb];
        const uint4 vva = *(const uint4*)&Vg[rowa];
        const uint4 vvb = *(const uint4*)&Vg[rowb];
        __syncthreads();   // previous round's compute done reading smem

        // K tiles [key][dim]: rotated u32 stores (conflict-free)
        {
            uint32_t ka[4] = {kva.x, kva.y, kva.z, kva.w};
            uint32_t kb[4] = {kvb.x, kvb.y, kvb.z, kvb.w};
            #pragma unroll
            for (int j = 0; j < 4; j++) {
                const int jj = (j + kr) & 3;
                *(uint32_t*)&Ks[kr][q4 * 8 + 2 * jj] = ka[jj];
                *(uint32_t*)&Ks[64 + kr][q4 * 8 + 2 * jj] = kb[jj];
            }
        }
        // V^T tiles [dim][token]: shfl partner token, byte_perm merge, swizzled
        {
            const int pk = kr & 1;
            uint32_t va[4] = {vva.x, vva.y, vva.z, vva.w};
            uint32_t vb[4] = {vvb.x, vvb.y, vvb.z, vvb.w};
            #pragma unroll
            for (int j = 0; j < 4; j++) {
                const uint32_t pa = __shfl_xor_sync(0xffffffffu, va[j], 4);
                const uint32_t pb = __shfl_xor_sync(0xffffffffu, vb[j], 4);
                const uint32_t worda = pk ? __byte_perm(pa, va[j], 0x7632)
                                          : __byte_perm(va[j], pa, 0x5410);
                const uint32_t wordb = pk ? __byte_perm(pb, vb[j], 0x7632)
                                          : __byte_perm(vb[j], pb, 0x5410);
                const int d = q4 * 8 + 2 * j + pk;
                const int pos = (kr >> 1) ^ (((d >> 3) & 3) << 3);
                *(uint32_t*)&VTs[0][d][2 * pos] = worda;
                *(uint32_t*)&VTs[1][d][2 * pos] = wordb;
            }
        }
        __syncthreads();

        #pragma unroll
        for (int sub = 0; sub < 2; sub++) {
            // ---- S = Q K^T (S in log2 domain via Q prescale) ----
            float sacc[8][4];
            #pragma unroll
            for (int nf = 0; nf < 8; nf++) {
                sacc[nf][0] = sacc[nf][1] = sacc[nf][2] = sacc[nf][3] = 0.0f;
                const int key = sub * 64 + nf * 8 + g;
                #pragma unroll
                for (int kf = 0; kf < 2; kf++) {
                    const uint32_t b0 = *(const uint32_t*)&Ks[key][kf * 16 + 2 * q];
                    const uint32_t b1 = *(const uint32_t*)&Ks[key][kf * 16 + 2 * q + 8];
                    MMA_F16(sacc[nf], qf[kf], b0, b1);
                }
            }

            // ---- P = 2^S via ex2.f16x2 (no extra scale), pack P frags ----
            uint32_t pf[4][4];
            #pragma unroll
            for (int nf = 0; nf < 8; nf++) {
                const uint32_t pa = ex2h2(packh2(sacc[nf][0], sacc[nf][1]));
                const uint32_t pb = ex2h2(packh2(sacc[nf][2], sacc[nf][3]));
                const int kp = nf >> 1, half = nf & 1;
                pf[kp][half * 2 + 0] = pa;
                pf[kp][half * 2 + 1] = pb;
            }

            // ---- row sums via HADD2 on pf (fma pipe; per-sub fp32 fold) ----
            {
                uint32_t a0 = hadd2u(pf[0][0], pf[0][2]);
                uint32_t a1 = hadd2u(pf[0][1], pf[0][3]);
                #pragma unroll
                for (int kp = 1; kp < 4; kp++) {
                    a0 = hadd2u(a0, hadd2u(pf[kp][0], pf[kp][2]));
                    a1 = hadd2u(a1, hadd2u(pf[kp][1], pf[kp][3]));
                }
                const float2 f0 = __half22float2(*reinterpret_cast<__half2*>(&a0));
                const float2 f1 = __half22float2(*reinterpret_cast<__half2*>(&a1));
                lsum0 += f0.x + f0.y;
                lsum1 += f1.x + f1.y;
            }

            // ---- O += P V ----
            #pragma unroll
            for (int of = 0; of < 4; of++) {
                const int d = of * 8 + g;
                const int sw = ((d >> 3) & 3) << 3;
                #pragma unroll
                for (int kp = 0; kp < 4; kp++) {
                    const int lw0 = q + 8 * kp;
                    const uint32_t b0 = *(const uint32_t*)&VTs[sub][d][2 * (lw0 ^ sw)];
                    const uint32_t b1 = *(const uint32_t*)&VTs[sub][d][2 * ((lw0 + 4) ^ sw)];
                    MMA_F16(oacc[of], pf[kp], b0, b1);
                }
            }
        }
    }

    // ---- reduce row sums across the 4 lanes of each row group ----
    lsum0 += __shfl_xor_sync(0xffffffffu, lsum0, 1);
    lsum0 += __shfl_xor_sync(0xffffffffu, lsum0, 2);
    lsum1 += __shfl_xor_sync(0xffffffffu, lsum1, 1);
    lsum1 += __shfl_xor_sync(0xffffffffu, lsum1, 2);
    const float inv0 = 1.0f / lsum0;
    const float inv1 = 1.0f / lsum1;

    // ---- write O (fp16) ----
    {
        const int b = bh >> 2, h = bh & 3;
        const int grow0 = qt * 128 + r0l;
        __half* dst0 = g_AO + ((size_t)(b * NTOK + grow0)) * ADIM + h * HDIM;
        __half* dst1 = dst0 + 8 * ADIM;
        #pragma unroll
        for (int of = 0; of < 4; of++) {
            const int c = of * 8 + 2 * q;
            *(uint32_t*)&dst0[c] = packh2(oacc[of][0] * inv0, oacc[of][1] * inv0);
            *(uint32_t*)&dst1[c] = packh2(oacc[of][2] * inv1, oacc[of][3] * inv1);
        }
    }
}

// ---------------------------------------------------------------------------
// Kernel 3: output projection via HMMA (R10 exact).
// grid = (2, 128), 256 threads = 8 warps (4 M x 2 N). CTA tile M=64, N=128.
// ---------------------------------------------------------------------------
#define WOT_STRIDE 136
__global__ void __launch_bounds__(256) oproj_mma(const float* __restrict__ Wo,
                                                 float* __restrict__ out) {
    __shared__ __half WoT[128 * WOT_STRIDE];
    const int bn = blockIdx.x;
    const int bm = blockIdx.y;
    const int t = threadIdx.x;
    const int w = t >> 5, lane = t & 31;
    const int g = lane >> 2, q = lane & 3;
    const int wm = w >> 1, wn = w & 1;

    {
        const int n = t & 127, kb = (t >> 7) * 64;
        #pragma unroll
        for (int kk = 0; kk < 64; kk += 8) {
            const int k0 = kb + kk;
            __half h[8];
            #pragma unroll
            for (int j = 0; j < 8; j++)
                h[j] = __float2half_rn(Wo[(size_t)(k0 + j) * CDIM + bn * 128 + n]);
            *(uint4*)&WoT[n * WOT_STRIDE + k0] = *(uint4*)h;
        }
    }
    __syncthreads();

    const int r0 = bm * 64 + wm * 16 + g;
    float acc[8][4] = {};
    const __half* Arow0 = g_AO + (size_t)r0 * ADIM;
    const __half* Wrow = &WoT[(wn * 64 + g) * WOT_STRIDE + 2 * q];

    #pragma unroll
    for (int k0 = 0; k0 < ADIM; k0 += 16) {
        uint32_t af[4];
        af[0] = *(const uint32_t*)&Arow0[k0 + 2 * q];
        af[1] = *(const uint32_t*)&Arow0[8 * ADIM + k0 + 2 * q];
        af[2] = *(const uint32_t*)&Arow0[k0 + 2 * q + 8];
        af[3] = *(const uint32_t*)&Arow0[8 * ADIM + k0 + 2 * q + 8];
        #pragma unroll
        for (int nf = 0; nf < 8; nf++) {
            const uint32_t b0 = *(const uint32_t*)&Wrow[nf * 8 * WOT_STRIDE + k0];
            const uint32_t b1 = *(const uint32_t*)&Wrow[nf * 8 * WOT_STRIDE + k0 + 8];
            MMA_F16(acc[nf], af, b0, b1);
        }
    }

    #pragma unroll
    for (int nf = 0; nf < 8; nf++) {
        const int c = bn * 128 + wn * 64 + nf * 8 + 2 * q;
        *(float2*)&out[(size_t)r0 * CDIM + c] = make_float2(acc[nf][0], acc[nf][1]);
        *(float2*)&out[(size_t)(r0 + 8) * CDIM + c] = make_float2(acc[nf][2], acc[nf][3]);
    }
}

// ---------------------------------------------------------------------------
extern "C" void kernel_launch(void* const* d_in, const int* in_sizes, int n_in,
                              void* d_out, int out_size) {
    const float* query   = (const float*)d_in[0];
    const float* context = (const float*)d_in[1];
    const float* Wq      = (const float*)d_in[2];
    const float* Wk      = (const float*)d_in[3];
    const float* Wv      = (const float*)d_in[4];
    const float* Wo      = (const float*)d_in[5];
    float* out = (float*)d_out;

    const int qkv_smem = 128 * WT_STRIDE * 2;  // 67.6 KB > 48 KB -> opt-in
    cudaFuncSetAttribute(qkv_proj_mma, cudaFuncAttributeMaxDynamicSharedMemorySize, qkv_smem);

    qkv_proj_mma<<<dim3(128, 3), 256, qkv_smem>>>(query, context, Wq, Wk, Wv);
    flash_attn_mma<<<dim3(NTOK / 128, NH * BATCH), 256>>>();
    oproj_mma<<<dim3(2, 128), 256>>>(Wo, out);
}

// round 14
// speedup vs baseline: 1.1686x; 1.0185x over previous
#include <cuda_runtime.h>
#include <cuda_fp16.h>
#include <stdint.h>
#include <math.h>

// Problem constants
#define BATCH 2
#define NTOK  4096
#define CDIM  256
#define ADIM  128
#define NH    4
#define HDIM  32
#define QSCALE 0.17677669529663688f   // 1/sqrt(32)
#define LOG2E  1.4426950408889634f
#define QSCALE_L2E (QSCALE * LOG2E)   // folded: S comes out in log2 domain

// Scratch (allocation-free: __device__ globals) — fp16 dataflow
__device__ __half g_Q[BATCH * NH * NTOK * HDIM];   // prescaled by QSCALE*LOG2E
__device__ __half g_K[BATCH * NH * NTOK * HDIM];
__device__ __half g_V[BATCH * NH * NTOK * HDIM];
__device__ __half g_AO[BATCH * NTOK * ADIM];

// m16n8k16 fp16 HMMA, fp32 accum, D=C in place (baseline PTX, compute_103-safe)
#define MMA_F16(d, a, b0, b1) \
    asm volatile("mma.sync.aligned.m16n8k16.row.col.f32.f16.f16.f32 " \
        "{%0,%1,%2,%3}, {%4,%5,%6,%7}, {%8,%9}, {%0,%1,%2,%3};" \
        : "+f"((d)[0]), "+f"((d)[1]), "+f"((d)[2]), "+f"((d)[3]) \
        : "r"((a)[0]), "r"((a)[1]), "r"((a)[2]), "r"((a)[3]), "r"(b0), "r"(b1))

#define CP_ASYNC16(dst, src) \
    asm volatile("cp.async.cg.shared.global [%0], [%1], 16;" :: "r"(dst), "l"(src))
#define CP_COMMIT() asm volatile("cp.async.commit_group;")
#define CP_WAIT2()  asm volatile("cp.async.wait_group 2;")

__device__ __forceinline__ uint32_t packh2(float a, float b) {
    __half2 t = __floats2half2_rn(a, b);   // low = a
    return *reinterpret_cast<uint32_t*>(&t);
}
__device__ __forceinline__ uint32_t ex2h2(uint32_t x) {
    uint32_t r;
    asm("ex2.approx.f16x2 %0, %1;" : "=r"(r) : "r"(x));
    return r;
}
__device__ __forceinline__ uint32_t hadd2u(uint32_t a, uint32_t b) {
    uint32_t r;
    asm("add.f16x2 %0, %1, %2;" : "=r"(r) : "r"(a), "r"(b));
    return r;
}
__device__ __forceinline__ uint32_t smem_u32(const void* p) {
    uint32_t a;
    asm("{ .reg .u64 t; cvta.to.shared.u64 t, %1; cvt.u32.u64 %0, t; }" : "=r"(a) : "l"(p));
    return a;
}

// ---------------------------------------------------------------------------
// Kernel 1: fused QKV projection via HMMA + cp.async X pipeline.
// grid = (128, 3), 256 threads = 8 warps (4 M x 2 N). CTA tile M=64, N=128.
// W^T staged once; X streamed through 4 cp.async stages (prefetch dist 3).
// ---------------------------------------------------------------------------
#define WT_STRIDE 264
#define XS_STRIDE 20                    // floats; 80B rows (16B-aligned for cp.async)
#define QKV_WT_BYTES (128 * WT_STRIDE * 2)                    // 67584
#define QKV_SMEM (QKV_WT_BYTES + 4 * 64 * XS_STRIDE * 4)      // + 20480 = 88064
__global__ void __launch_bounds__(256) qkv_proj_mma(const float* __restrict__ query,
                                                    const float* __restrict__ context,
                                                    const float* __restrict__ Wq,
                                                    const float* __restrict__ Wk,
                                                    const float* __restrict__ Wv) {
    extern __shared__ char dynsm[];
    __half* WT = (__half*)dynsm;                       // [128][WT_STRIDE]
    float*  Xs = (float*)(dynsm + QKV_WT_BYTES);       // [4][64][XS_STRIDE]

    const int bm = blockIdx.x;
    const int which = blockIdx.y;
    const float* X = (which == 0) ? query : context;
    const float* W = (which == 0) ? Wq : ((which == 1) ? Wk : Wv);
    __half* Og = (which == 0) ? g_Q : ((which == 1) ? g_K : g_V);

    const int t = threadIdx.x;
    const int w = t >> 5, lane = t & 31;
    const int g = lane >> 2, q = lane & 3;
    const int wm = w >> 1, wn = w & 1;

    const int xrow = t >> 2;            // 0..63
    const int xcol4 = (t & 3) * 4;      // float offset of this thread's 16B chunk
    const uint32_t xs_base = smem_u32(Xs);
    const float* xsrc_row = X + (size_t)(bm * 64 + xrow) * CDIM + xcol4;

    // ---- prologue: issue X stages for tiles 0,1,2 ----
    #pragma unroll
    for (int kt = 0; kt < 3; kt++) {
        const uint32_t dst = xs_base + (uint32_t)(((kt & 3) * 64 + xrow) * XS_STRIDE + xcol4) * 4u;
        CP_ASYNC16(dst, xsrc_row + kt * 16);
        CP_COMMIT();
    }

    // ---- stage W^T (fp16) ----
    {
        const int n = t & 127, kb = (t >> 7) * 128;
        #pragma unroll
        for (int kk = 0; kk < 128; kk += 8) {
            const int k0 = kb + kk;
            __half h[8];
            #pragma unroll
            for (int j = 0; j < 8; j++)
                h[j] = __float2half_rn(W[(size_t)(k0 + j) * ADIM + n]);
            *(uint4*)&WT[n * WT_STRIDE + k0] = *(uint4*)h;
        }
    }

    const int r0 = bm * 64 + wm * 16 + g;
    float acc[8][4] = {};
    const __half* Wrow = &WT[(wn * 64 + g) * WT_STRIDE + 2 * q];
    const int fr0 = (wm * 16 + g) * XS_STRIDE + 2 * q;   // local frag row offset

    #pragma unroll
    for (int kt = 0; kt < 16; kt++) {
        CP_WAIT2();
        __syncthreads();   // tile kt visible to all; slot (kt-1)%4 reads all done
        {
            const int nt = kt + 3;
            if (nt < 16) {
                const uint32_t dst = xs_base + (uint32_t)(((nt & 3) * 64 + xrow) * XS_STRIDE + xcol4) * 4u;
                CP_ASYNC16(dst, xsrc_row + nt * 16);
            }
            CP_COMMIT();   // always commit: keeps group accounting exact
        }
        uint32_t af[4];
        {
            const float* xs = Xs + (kt & 3) * 64 * XS_STRIDE;
            const float2 x0 = *(const float2*)&xs[fr0];
            const float2 x1 = *(const float2*)&xs[fr0 + 8 * XS_STRIDE];
            const float2 x2 = *(const float2*)&xs[fr0 + 8];
            const float2 x3 = *(const float2*)&xs[fr0 + 8 * XS_STRIDE + 8];
            af[0] = packh2(x0.x, x0.y);
            af[1] = packh2(x1.x, x1.y);
            af[2] = packh2(x2.x, x2.y);
            af[3] = packh2(x3.x, x3.y);
        }
        #pragma unroll
        for (int nf = 0; nf < 8; nf++) {
            const uint32_t b0 = *(const uint32_t*)&Wrow[nf * 8 * WT_STRIDE + kt * 16];
            const uint32_t b1 = *(const uint32_t*)&Wrow[nf * 8 * WT_STRIDE + kt * 16 + 8];
            MMA_F16(acc[nf], af, b0, b1);
        }
    }

    // ---- epilogue: fp16 out, [b,head,tok,32], Q prescaled by QSCALE*LOG2E ----
    const float scale = (which == 0) ? QSCALE_L2E : 1.0f;
    const int bb = r0 >> 12, ii = r0 & 4095;
    #pragma unroll
    for (int nf = 0; nf < 8; nf++) {
        const int c = wn * 64 + nf * 8 + 2 * q;
        const int hh = c >> 5, dd = c & 31;
        const size_t base = (((size_t)(bb * NH + hh) * NTOK) + ii) * HDIM + dd;
        *(uint32_t*)&Og[base] = packh2(acc[nf][0] * scale, acc[nf][1] * scale);
        *(uint32_t*)&Og[base + 8 * HDIM] = packh2(acc[nf][2] * scale, acc[nf][3] * scale);
    }
}

// ---------------------------------------------------------------------------
// Kernel 2: flash attention (R13 exact). fp16 in/out, ex2.f16x2 exp,
// rowsum via HADD2. grid = (32, 8), 256 threads; 128 keys per sync round.
// ---------------------------------------------------------------------------
__global__ void __launch_bounds__(256) flash_attn_mma() {
    __shared__ __half Ks[128][40];
    __shared__ __half VTs[2][32][72];

    const int qt = blockIdx.x;
    const int bh = blockIdx.y;
    const int t  = threadIdx.x;
    const int w  = t >> 5;
    const int lane = t & 31;
    const int g = lane >> 2;
    const int q = lane & 3;

    const __half* Qg = g_Q + ((size_t)bh * NTOK + (size_t)qt * 128) * HDIM;
    const __half* Kg = g_K + (size_t)bh * NTOK * HDIM;
    const __half* Vg = g_V + (size_t)bh * NTOK * HDIM;

    const int r0l = w * 16 + g;
    uint32_t qf[2][4];
    #pragma unroll
    for (int kf = 0; kf < 2; kf++) {
        qf[kf][0] = *(const uint32_t*)&Qg[(size_t)r0l * HDIM + kf * 16 + 2 * q];
        qf[kf][1] = *(const uint32_t*)&Qg[(size_t)(r0l + 8) * HDIM + kf * 16 + 2 * q];
        qf[kf][2] = *(const uint32_t*)&Qg[(size_t)r0l * HDIM + kf * 16 + 2 * q + 8];
        qf[kf][3] = *(const uint32_t*)&Qg[(size_t)(r0l + 8) * HDIM + kf * 16 + 2 * q + 8];
    }

    float oacc[4][4] = {};
    float lsum0 = 0.0f, lsum1 = 0.0f;

    const int kr = t >> 2;
    const int q4 = t & 3;

    for (int kt = 0; kt < NTOK / 128; kt++) {
        const size_t rowa = ((size_t)kt * 128 + kr) * HDIM + q4 * 8;
        const size_t rowb = rowa + (size_t)64 * HDIM;
        const uint4 kva = *(const uint4*)&Kg[rowa];
        const uint4 kvb = *(const uint4*)&Kg[rowb];
        const uint4 vva = *(const uint4*)&Vg[rowa];
        const uint4 vvb = *(const uint4*)&Vg[rowb];
        __syncthreads();

        {
            uint32_t ka[4] = {kva.x, kva.y, kva.z, kva.w};
            uint32_t kb[4] = {kvb.x, kvb.y, kvb.z, kvb.w};
            #pragma unroll
            for (int j = 0; j < 4; j++) {
                const int jj = (j + kr) & 3;
                *(uint32_t*)&Ks[kr][q4 * 8 + 2 * jj] = ka[jj];
                *(uint32_t*)&Ks[64 + kr][q4 * 8 + 2 * jj] = kb[jj];
            }
        }
        {
            const int pk = kr & 1;
            uint32_t va[4] = {vva.x, vva.y, vva.z, vva.w};
            uint32_t vb[4] = {vvb.x, vvb.y, vvb.z, vvb.w};
            #pragma unroll
            for (int j = 0; j < 4; j++) {
                const uint32_t pa = __shfl_xor_sync(0xffffffffu, va[j], 4);
                const uint32_t pb = __shfl_xor_sync(0xffffffffu, vb[j], 4);
                const uint32_t worda = pk ? __byte_perm(pa, va[j], 0x7632)
                                          : __byte_perm(va[j], pa, 0x5410);
                const uint32_t wordb = pk ? __byte_perm(pb, vb[j], 0x7632)
                                          : __byte_perm(vb[j], pb, 0x5410);
                const int d = q4 * 8 + 2 * j + pk;
                const int pos = (kr >> 1) ^ (((d >> 3) & 3) << 3);
                *(uint32_t*)&VTs[0][d][2 * pos] = worda;
                *(uint32_t*)&VTs[1][d][2 * pos] = wordb;
            }
        }
        __syncthreads();

        #pragma unroll
        for (int sub = 0; sub < 2; sub++) {
            float sacc[8][4];
            #pragma unroll
            for (int nf = 0; nf < 8; nf++) {
                sacc[nf][0] = sacc[nf][1] = sacc[nf][2] = sacc[nf][3] = 0.0f;
                const int key = sub * 64 + nf * 8 + g;
                #pragma unroll
                for (int kf = 0; kf < 2; kf++) {
                    const uint32_t b0 = *(const uint32_t*)&Ks[key][kf * 16 + 2 * q];
                    const uint32_t b1 = *(const uint32_t*)&Ks[key][kf * 16 + 2 * q + 8];
                    MMA_F16(sacc[nf], qf[kf], b0, b1);
                }
            }

            uint32_t pf[4][4];
            #pragma unroll
            for (int nf = 0; nf < 8; nf++) {
                const uint32_t pa = ex2h2(packh2(sacc[nf][0], sacc[nf][1]));
                const uint32_t pb = ex2h2(packh2(sacc[nf][2], sacc[nf][3]));
                const int kp = nf >> 1, half = nf & 1;
                pf[kp][half * 2 + 0] = pa;
                pf[kp][half * 2 + 1] = pb;
            }

            {
                uint32_t a0 = hadd2u(pf[0][0], pf[0][2]);
                uint32_t a1 = hadd2u(pf[0][1], pf[0][3]);
                #pragma unroll
                for (int kp = 1; kp < 4; kp++) {
                    a0 = hadd2u(a0, hadd2u(pf[kp][0], pf[kp][2]));
                    a1 = hadd2u(a1, hadd2u(pf[kp][1], pf[kp][3]));
                }
                const float2 f0 = __half22float2(*reinterpret_cast<__half2*>(&a0));
                const float2 f1 = __half22float2(*reinterpret_cast<__half2*>(&a1));
                lsum0 += f0.x + f0.y;
                lsum1 += f1.x + f1.y;
            }

            #pragma unroll
            for (int of = 0; of < 4; of++) {
                const int d = of * 8 + g;
                const int sw = ((d >> 3) & 3) << 3;
                #pragma unroll
                for (int kp = 0; kp < 4; kp++) {
                    const int lw0 = q + 8 * kp;
                    const uint32_t b0 = *(const uint32_t*)&VTs[sub][d][2 * (lw0 ^ sw)];
                    const uint32_t b1 = *(const uint32_t*)&VTs[sub][d][2 * ((lw0 + 4) ^ sw)];
                    MMA_F16(oacc[of], pf[kp], b0, b1);
                }
            }
        }
    }

    lsum0 += __shfl_xor_sync(0xffffffffu, lsum0, 1);
    lsum0 += __shfl_xor_sync(0xffffffffu, lsum0, 2);
    lsum1 += __shfl_xor_sync(0xffffffffu, lsum1, 1);
    lsum1 += __shfl_xor_sync(0xffffffffu, lsum1, 2);
    const float inv0 = 1.0f / lsum0;
    const float inv1 = 1.0f / lsum1;

    {
        const int b = bh >> 2, h = bh & 3;
        const int grow0 = qt * 128 + r0l;
        __half* dst0 = g_AO + ((size_t)(b * NTOK + grow0)) * ADIM + h * HDIM;
        __half* dst1 = dst0 + 8 * ADIM;
        #pragma unroll
        for (int of = 0; of < 4; of++) {
            const int c = of * 8 + 2 * q;
            *(uint32_t*)&dst0[c] = packh2(oacc[of][0] * inv0, oacc[of][1] * inv0);
            *(uint32_t*)&dst1[c] = packh2(oacc[of][2] * inv1, oacc[of][3] * inv1);
        }
    }
}

// ---------------------------------------------------------------------------
// Kernel 3: output projection via HMMA; all A-frag LDGs hoisted (MLP=32).
// grid = (2, 128), 256 threads = 8 warps (4 M x 2 N). CTA tile M=64, N=128.
// ---------------------------------------------------------------------------
#define WOT_STRIDE 136
__global__ void __launch_bounds__(256) oproj_mma(const float* __restrict__ Wo,
                                                 float* __restrict__ out) {
    __shared__ __half WoT[128 * WOT_STRIDE];
    const int bn = blockIdx.x;
    const int bm = blockIdx.y;
    const int t = threadIdx.x;
    const int w = t >> 5, lane = t & 31;
    const int g = lane >> 2, q = lane & 3;
    const int wm = w >> 1, wn = w & 1;

    const int r0 = bm * 64 + wm * 16 + g;
    const __half* Arow0 = g_AO + (size_t)r0 * ADIM;

    // ---- hoist all A-fragments (32 independent LDGs; overlap W staging) ----
    uint32_t af[8][4];
    #pragma unroll
    for (int ks = 0; ks < 8; ks++) {
        const int k0 = ks * 16;
        af[ks][0] = *(const uint32_t*)&Arow0[k0 + 2 * q];
        af[ks][1] = *(const uint32_t*)&Arow0[8 * ADIM + k0 + 2 * q];
        af[ks][2] = *(const uint32_t*)&Arow0[k0 + 2 * q + 8];
        af[ks][3] = *(const uint32_t*)&Arow0[8 * ADIM + k0 + 2 * q + 8];
    }

    {
        const int n = t & 127, kb = (t >> 7) * 64;
        #pragma unroll
        for (int kk = 0; kk < 64; kk += 8) {
            const int k0 = kb + kk;
            __half h[8];
            #pragma unroll
            for (int j = 0; j < 8; j++)
                h[j] = __float2half_rn(Wo[(size_t)(k0 + j) * CDIM + bn * 128 + n]);
            *(uint4*)&WoT[n * WOT_STRIDE + k0] = *(uint4*)h;
        }
    }
    __syncthreads();

    float acc[8][4] = {};
    const __half* Wrow = &WoT[(wn * 64 + g) * WOT_STRIDE + 2 * q];

    #pragma unroll
    for (int ks = 0; ks < 8; ks++) {
        const int k0 = ks * 16;
        #pragma unroll
        for (int nf = 0; nf < 8; nf++) {
            const uint32_t b0 = *(const uint32_t*)&Wrow[nf * 8 * WOT_STRIDE + k0];
            const uint32_t b1 = *(const uint32_t*)&Wrow[nf * 8 * WOT_STRIDE + k0 + 8];
            MMA_F16(acc[nf], af[ks], b0, b1);
        }
    }

    #pragma unroll
    for (int nf = 0; nf < 8; nf++) {
        const int c = bn * 128 + wn * 64 + nf * 8 + 2 * q;
        *(float2*)&out[(size_t)r0 * CDIM + c] = make_float2(acc[nf][0], acc[nf][1]);
        *(float2*)&out[(size_t)(r0 + 8) * CDIM + c] = make_float2(acc[nf][2], acc[nf][3]);
    }
}

// ---------------------------------------------------------------------------
extern "C" void kernel_launch(void* const* d_in, const int* in_sizes, int n_in,
                              void* d_out, int out_size) {
    const float* query   = (const float*)d_in[0];
    const float* context = (const float*)d_in[1];
    const float* Wq      = (const float*)d_in[2];
    const float* Wk      = (const float*)d_in[3];
    const float* Wv      = (const float*)d_in[4];
    const float* Wo      = (const float*)d_in[5];
    float* out = (float*)d_out;

    cudaFuncSetAttribute(qkv_proj_mma, cudaFuncAttributeMaxDynamicSharedMemorySize, QKV_SMEM);

    qkv_proj_mma<<<dim3(128, 3), 256, QKV_SMEM>>>(query, context, Wq, Wk, Wv);
    flash_attn_mma<<<dim3(NTOK / 128, NH * BATCH), 256>>>();
    oproj_mma<<<dim3(2, 128), 256>>>(Wo, out);
}